// round 1
// baseline (speedup 1.0000x reference)
#include <cuda_runtime.h>

#define NPTS 4096
#define JCH 16          // j chunks
#define JPER (NPTS/JCH) // 256
#define IBLK 16         // i blocks
#define TPB 256
#define STEPS 10

// Scratch (no allocations allowed)
__device__ float g_pcA[NPTS*3];
__device__ float g_pcB[NPTS*3];
__device__ float g_match[NPTS*3];
__device__ unsigned long long g_part[JCH*NPTS];
__device__ float g_RT[12];   // R row-major [0..8], t [9..11]

// ---------------------------------------------------------------------------
// K1: (optionally apply previous R,t to pc), then brute-force NN partial argmin
// over this block's j-chunk. grid = (IBLK, JCH), block = TPB.
// ---------------------------------------------------------------------------
__global__ void k_nn(const float* __restrict__ pc_in, float* __restrict__ pc_out,
                     const float* __restrict__ p2, int apply)
{
    __shared__ float sj[JPER*3];
    const int jb  = blockIdx.y;
    const int tid = threadIdx.x;
    for (int k = tid; k < JPER*3; k += TPB) sj[k] = p2[jb*(JPER*3) + k];

    const int i = blockIdx.x*TPB + tid;
    float px = pc_in[i*3+0], py = pc_in[i*3+1], pz = pc_in[i*3+2];
    if (apply) {
        float qx = g_RT[0]*px + g_RT[1]*py + g_RT[2]*pz + g_RT[9];
        float qy = g_RT[3]*px + g_RT[4]*py + g_RT[5]*pz + g_RT[10];
        float qz = g_RT[6]*px + g_RT[7]*py + g_RT[8]*pz + g_RT[11];
        px = qx; py = qy; pz = qz;
        if (jb == 0) {  // one chunk materializes the updated cloud
            pc_out[i*3+0] = px; pc_out[i*3+1] = py; pc_out[i*3+2] = pz;
        }
    }
    __syncthreads();

    float bestd = 3.4028235e38f;
    int   bestj = 0;
    #pragma unroll 8
    for (int jj = 0; jj < JPER; jj++) {
        float dx = px - sj[3*jj+0];
        float dy = py - sj[3*jj+1];
        float dz = pz - sj[3*jj+2];
        float d  = fmaf(dx,dx, fmaf(dy,dy, dz*dz));
        if (d < bestd) { bestd = d; bestj = jb*JPER + jj; }  // strict <: first index on ties
    }
    g_part[jb*NPTS + i] =
        ((unsigned long long)__float_as_uint(bestd) << 32) | (unsigned int)bestj;
}

// ---------------------------------------------------------------------------
// K2: reduce partial argmins across j-chunks, gather matched p2 points.
// grid = IBLK, block = TPB.
// ---------------------------------------------------------------------------
__global__ void k_gather(const float* __restrict__ p2)
{
    const int i = blockIdx.x*TPB + threadIdx.x;
    unsigned long long best = g_part[i];
    #pragma unroll
    for (int jb = 1; jb < JCH; jb++) {
        unsigned long long v = g_part[jb*NPTS + i];
        if (v < best) best = v;   // lower j wins on equal dist -> first argmin
    }
    const int idx = (int)(unsigned int)best;
    g_match[i*3+0] = p2[idx*3+0];
    g_match[i*3+1] = p2[idx*3+1];
    g_match[i*3+2] = p2[idx*3+2];
}

// ---------------------------------------------------------------------------
// Kabsch solve from 3x3 cross-covariance (double precision, single thread).
// R = V * diag(1,1,det(V U^T)) * U^T ; t = c2 - R c1
// ---------------------------------------------------------------------------
__device__ void kabsch_from_H(const double H[3][3],
                              const double c1[3], const double c2[3],
                              double R[3][3], double t[3])
{
    // S = H^T H (symmetric PSD)
    double S[3][3], V[3][3];
    for (int r = 0; r < 3; r++)
        for (int c = 0; c < 3; c++) {
            double acc = 0.0;
            for (int k = 0; k < 3; k++) acc += H[k][r]*H[k][c];
            S[r][c] = acc;
            V[r][c] = (r == c) ? 1.0 : 0.0;
        }
    // cyclic Jacobi
    for (int sweep = 0; sweep < 12; sweep++) {
        for (int pair = 0; pair < 3; pair++) {
            int p = (pair == 2) ? 1 : 0;
            int q = (pair == 0) ? 1 : 2;
            double apq = S[p][q];
            if (fabs(apq) < 1e-300) continue;
            double theta = (S[q][q] - S[p][p]) / (2.0*apq);
            double tj = ((theta >= 0.0) ? 1.0 : -1.0) /
                        (fabs(theta) + sqrt(1.0 + theta*theta));
            double cj = 1.0/sqrt(1.0 + tj*tj);
            double sj = tj*cj;
            for (int k = 0; k < 3; k++) {
                double skp = S[k][p], skq = S[k][q];
                S[k][p] = cj*skp - sj*skq;
                S[k][q] = sj*skp + cj*skq;
            }
            for (int k = 0; k < 3; k++) {
                double spk = S[p][k], sqk = S[q][k];
                S[p][k] = cj*spk - sj*sqk;
                S[q][k] = sj*spk + cj*sqk;
            }
            for (int k = 0; k < 3; k++) {
                double vkp = V[k][p], vkq = V[k][q];
                V[k][p] = cj*vkp - sj*vkq;
                V[k][q] = sj*vkp + cj*vkq;
            }
        }
    }
    // sort eigenpairs descending
    double lam[3] = { S[0][0], S[1][1], S[2][2] };
    int ord[3] = {0,1,2};
    for (int a = 0; a < 2; a++)
        for (int b = a+1; b < 3; b++)
            if (lam[ord[b]] > lam[ord[a]]) { int tmp = ord[a]; ord[a] = ord[b]; ord[b] = tmp; }
    double Vs[3][3];
    for (int c = 0; c < 3; c++)
        for (int r = 0; r < 3; r++) Vs[r][c] = V[r][ord[c]];

    // U columns: u_i = H v_i / sigma_i
    double U[3][3];
    for (int c = 0; c < 3; c++) {
        double u0 = H[0][0]*Vs[0][c] + H[0][1]*Vs[1][c] + H[0][2]*Vs[2][c];
        double u1 = H[1][0]*Vs[0][c] + H[1][1]*Vs[1][c] + H[1][2]*Vs[2][c];
        double u2 = H[2][0]*Vs[0][c] + H[2][1]*Vs[1][c] + H[2][2]*Vs[2][c];
        double nrm = sqrt(u0*u0 + u1*u1 + u2*u2);
        if (nrm > 1e-30) { u0 /= nrm; u1 /= nrm; u2 /= nrm; }
        else if (c == 2) {  // rank-deficient fallback: u2 = u0 x u1
            u0 = U[1][0]*U[2][1] - U[2][0]*U[1][1];
            u1 = U[2][0]*U[0][1] - U[0][0]*U[2][1];
            u2 = U[0][0]*U[1][1] - U[1][0]*U[0][1];
        }
        U[0][c] = u0; U[1][c] = u1; U[2][c] = u2;
    }
    // det(V U^T) = det(V) * det(U)
    double detV = Vs[0][0]*(Vs[1][1]*Vs[2][2]-Vs[1][2]*Vs[2][1])
                - Vs[0][1]*(Vs[1][0]*Vs[2][2]-Vs[1][2]*Vs[2][0])
                + Vs[0][2]*(Vs[1][0]*Vs[2][1]-Vs[1][1]*Vs[2][0]);
    double detU = U[0][0]*(U[1][1]*U[2][2]-U[1][2]*U[2][1])
                - U[0][1]*(U[1][0]*U[2][2]-U[1][2]*U[2][0])
                + U[0][2]*(U[1][0]*U[2][1]-U[1][1]*U[2][0]);
    double d = (detV*detU < 0.0) ? -1.0 : 1.0;

    for (int r = 0; r < 3; r++)
        for (int c = 0; c < 3; c++)
            R[r][c] = Vs[r][0]*U[c][0] + Vs[r][1]*U[c][1] + d*Vs[r][2]*U[c][2];
    for (int r = 0; r < 3; r++)
        t[r] = c2[r] - (R[r][0]*c1[0] + R[r][1]*c1[1] + R[r][2]*c1[2]);
}

// ---------------------------------------------------------------------------
// K3: single-CTA two-pass centered covariance + Kabsch. grid=1, block=TPB.
// final_mode=0: write g_RT[12]; final_mode=1: write [3,4] output layout.
// ---------------------------------------------------------------------------
__global__ void k_solve(const float* __restrict__ src, const float* __restrict__ tgt,
                        float* __restrict__ out, int final_mode)
{
    __shared__ float red[9][TPB];
    __shared__ float cm[6];
    const int tid = threadIdx.x;

    // pass 1: sums -> means
    float a0=0.f,a1=0.f,a2=0.f,b0=0.f,b1=0.f,b2=0.f;
    for (int i = tid; i < NPTS; i += TPB) {
        a0 += src[i*3+0]; a1 += src[i*3+1]; a2 += src[i*3+2];
        b0 += tgt[i*3+0]; b1 += tgt[i*3+1]; b2 += tgt[i*3+2];
    }
    red[0][tid]=a0; red[1][tid]=a1; red[2][tid]=a2;
    red[3][tid]=b0; red[4][tid]=b1; red[5][tid]=b2;
    __syncthreads();
    for (int off = TPB/2; off > 0; off >>= 1) {
        if (tid < off)
            for (int q = 0; q < 6; q++) red[q][tid] += red[q][tid+off];
        __syncthreads();
    }
    if (tid == 0)
        for (int q = 0; q < 6; q++) cm[q] = red[q][0] * (1.0f/NPTS);
    __syncthreads();
    const float c1x=cm[0], c1y=cm[1], c1z=cm[2];
    const float c2x=cm[3], c2y=cm[4], c2z=cm[5];

    // pass 2: centered cross-covariance H[i][j] = sum (s_i)(d_j)
    float h[9];
    #pragma unroll
    for (int q = 0; q < 9; q++) h[q] = 0.f;
    for (int i = tid; i < NPTS; i += TPB) {
        float sx = src[i*3+0]-c1x, sy = src[i*3+1]-c1y, sz = src[i*3+2]-c1z;
        float dx = tgt[i*3+0]-c2x, dy = tgt[i*3+1]-c2y, dz = tgt[i*3+2]-c2z;
        h[0] += sx*dx; h[1] += sx*dy; h[2] += sx*dz;
        h[3] += sy*dx; h[4] += sy*dy; h[5] += sy*dz;
        h[6] += sz*dx; h[7] += sz*dy; h[8] += sz*dz;
    }
    __syncthreads();
    for (int q = 0; q < 9; q++) red[q][tid] = h[q];
    __syncthreads();
    for (int off = TPB/2; off > 0; off >>= 1) {
        if (tid < off)
            for (int q = 0; q < 9; q++) red[q][tid] += red[q][tid+off];
        __syncthreads();
    }

    if (tid == 0) {
        double H[3][3], c1[3], c2[3], R[3][3], t[3];
        for (int r = 0; r < 3; r++)
            for (int c = 0; c < 3; c++) H[r][c] = (double)red[r*3+c][0];
        c1[0]=c1x; c1[1]=c1y; c1[2]=c1z;
        c2[0]=c2x; c2[1]=c2y; c2[2]=c2z;
        kabsch_from_H(H, c1, c2, R, t);
        if (final_mode) {
            for (int r = 0; r < 3; r++) {
                out[r*4+0] = (float)R[r][0];
                out[r*4+1] = (float)R[r][1];
                out[r*4+2] = (float)R[r][2];
                out[r*4+3] = (float)t[r];
            }
        } else {
            for (int r = 0; r < 3; r++)
                for (int c = 0; c < 3; c++) out[r*3+c] = (float)R[r][c];
            out[9]=(float)t[0]; out[10]=(float)t[1]; out[11]=(float)t[2];
        }
    }
}

// ---------------------------------------------------------------------------
// K4: standalone transform (only used once, after the last solve).
// ---------------------------------------------------------------------------
__global__ void k_apply(const float* __restrict__ in, float* __restrict__ out)
{
    const int i = blockIdx.x*TPB + threadIdx.x;
    float px = in[i*3+0], py = in[i*3+1], pz = in[i*3+2];
    out[i*3+0] = g_RT[0]*px + g_RT[1]*py + g_RT[2]*pz + g_RT[9];
    out[i*3+1] = g_RT[3]*px + g_RT[4]*py + g_RT[5]*pz + g_RT[10];
    out[i*3+2] = g_RT[6]*px + g_RT[7]*py + g_RT[8]*pz + g_RT[11];
}

extern "C" void kernel_launch(void* const* d_in, const int* in_sizes, int n_in,
                              void* d_out, int out_size)
{
    const float* p1 = (const float*)d_in[0];
    const float* p2 = (const float*)d_in[1];
    float* out = (float*)d_out;

    float *A, *B, *M, *RT;
    cudaGetSymbolAddress((void**)&A,  g_pcA);
    cudaGetSymbolAddress((void**)&B,  g_pcB);
    cudaGetSymbolAddress((void**)&M,  g_match);
    cudaGetSymbolAddress((void**)&RT, g_RT);

    cudaMemcpyAsync(A, p1, NPTS*3*sizeof(float), cudaMemcpyDeviceToDevice, 0);

    const dim3 nng(IBLK, JCH);

    // iteration 0: pc_0 already in A, no transform to apply
    k_nn<<<nng, TPB>>>(A, B, p2, 0);
    k_gather<<<IBLK, TPB>>>(p2);
    k_solve<<<1, TPB>>>(A, M, RT, 0);

    float* cur = A;  // holds pc_k at start of iteration k
    for (int k = 1; k < STEPS; k++) {
        float* inb  = cur;
        float* outb = (cur == A) ? B : A;
        // apply R_{k-1},t_{k-1} on the fly; jb==0 materializes pc_k in outb
        k_nn<<<nng, TPB>>>(inb, outb, p2, 1);
        k_gather<<<IBLK, TPB>>>(p2);
        k_solve<<<1, TPB>>>(outb, M, RT, 0);
        cur = outb;
    }

    // materialize pc_STEPS with the last R,t, then final Kabsch(p1 -> pc_final)
    float* fin = (cur == A) ? B : A;
    k_apply<<<IBLK, TPB>>>(cur, fin);
    k_solve<<<1, TPB>>>(p1, fin, out, 1);
}

// round 2
// speedup vs baseline: 8.9594x; 8.9594x over previous
#include <cuda_runtime.h>

#define NPTS 4096
#define TPB  256
#define PPT  4                         // points per thread in k_nn
#define IBLK (NPTS/(TPB*PPT))          // 4
#define JCH  32                        // j chunks
#define JPER (NPTS/JCH)                // 128
#define TPB2 512
#define STEPS 10

// Scratch (no allocations allowed)
__device__ float g_pcA[NPTS*3];
__device__ float g_pcB[NPTS*3];
__device__ unsigned long long g_best[NPTS];
__device__ float g_RT[12];   // R row-major [0..8], t [9..11]

// Monotone float->uint key (works for negative scores)
__device__ __forceinline__ unsigned int fkey(float f) {
    unsigned int u = __float_as_uint(f);
    return (u & 0x80000000u) ? ~u : (u | 0x80000000u);
}

// ---------------------------------------------------------------------------
// K1: (optionally apply previous R,t), then brute-force NN partial argmin over
// this block's j-chunk using score = |q|^2/2 - p.q (argmin-equivalent).
// Cross-chunk combine via atomicMin on a sortable (score,j) u64 key.
// grid = (IBLK, JCH), block = TPB.
// ---------------------------------------------------------------------------
__global__ void __launch_bounds__(TPB) k_nn(const float* __restrict__ pc_in,
                                            float* __restrict__ pc_out,
                                            const float* __restrict__ p2,
                                            int apply)
{
    __shared__ float4 sj[JPER];
    const int jb  = blockIdx.y;
    const int tid = threadIdx.x;
    if (tid < JPER) {
        int j = jb*JPER + tid;
        float qx = p2[j*3+0], qy = p2[j*3+1], qz = p2[j*3+2];
        sj[tid] = make_float4(qx, qy, qz, 0.5f*fmaf(qx,qx,fmaf(qy,qy,qz*qz)));
    }

    const int base = blockIdx.x*TPB + tid;     // 4-point group id
    const float4* pin = (const float4*)pc_in;
    float4 v0 = pin[base*3+0], v1 = pin[base*3+1], v2 = pin[base*3+2];
    float x0=v0.x, y0=v0.y, z0=v0.z;
    float x1=v0.w, y1=v1.x, z1=v1.y;
    float x2=v1.z, y2=v1.w, z2=v2.x;
    float x3=v2.y, y3=v2.z, z3=v2.w;

    if (apply) {
        float r0=g_RT[0], r1=g_RT[1], r2=g_RT[2];
        float r3=g_RT[3], r4=g_RT[4], r5=g_RT[5];
        float r6=g_RT[6], r7=g_RT[7], r8=g_RT[8];
        float tx=g_RT[9], ty=g_RT[10], tz=g_RT[11];
        #define APPLY_RT(X,Y,Z) { \
            float nx = fmaf(r0,X, fmaf(r1,Y, fmaf(r2,Z, tx))); \
            float ny = fmaf(r3,X, fmaf(r4,Y, fmaf(r5,Z, ty))); \
            float nz = fmaf(r6,X, fmaf(r7,Y, fmaf(r8,Z, tz))); \
            X = nx; Y = ny; Z = nz; }
        APPLY_RT(x0,y0,z0) APPLY_RT(x1,y1,z1) APPLY_RT(x2,y2,z2) APPLY_RT(x3,y3,z3)
        #undef APPLY_RT
        if (jb == 0) {   // one chunk-row materializes the updated cloud
            float4* pout = (float4*)pc_out;
            pout[base*3+0] = make_float4(x0,y0,z0,x1);
            pout[base*3+1] = make_float4(y1,z1,x2,y2);
            pout[base*3+2] = make_float4(z2,x3,y3,z3);
        }
    }
    __syncthreads();

    float b0=3.4028235e38f, b1=b0, b2=b0, b3=b0;
    int   j0=0, j1=0, j2=0, j3=0;
    #pragma unroll 4
    for (int jj = 0; jj < JPER; jj++) {
        float4 q = sj[jj];
        float s0 = fmaf(-x0,q.x, fmaf(-y0,q.y, fmaf(-z0,q.z, q.w)));
        float s1 = fmaf(-x1,q.x, fmaf(-y1,q.y, fmaf(-z1,q.z, q.w)));
        float s2 = fmaf(-x2,q.x, fmaf(-y2,q.y, fmaf(-z2,q.z, q.w)));
        float s3 = fmaf(-x3,q.x, fmaf(-y3,q.y, fmaf(-z3,q.z, q.w)));
        if (s0 < b0) { b0 = s0; j0 = jj; }   // strict <: first index on ties
        if (s1 < b1) { b1 = s1; j1 = jj; }
        if (s2 < b2) { b2 = s2; j2 = jj; }
        if (s3 < b3) { b3 = s3; j3 = jj; }
    }

    const int i0 = base*PPT;
    atomicMin(&g_best[i0+0], ((unsigned long long)fkey(b0) << 32) | (unsigned)(jb*JPER + j0));
    atomicMin(&g_best[i0+1], ((unsigned long long)fkey(b1) << 32) | (unsigned)(jb*JPER + j1));
    atomicMin(&g_best[i0+2], ((unsigned long long)fkey(b2) << 32) | (unsigned)(jb*JPER + j2));
    atomicMin(&g_best[i0+3], ((unsigned long long)fkey(b3) << 32) | (unsigned)(jb*JPER + j3));
}

// ---------------------------------------------------------------------------
// Float Kabsch from raw product sums. P[r*3+c] = sum s_r d_c (uncentered),
// H = P - n*c1*c2^T. R = V diag(1,1,det) U^T, t = c2 - R c1.
// Runs on a single thread.
// ---------------------------------------------------------------------------
__device__ void kabsch3(const float* __restrict__ P, float n,
                        const float c1[3], const float c2[3],
                        float R[9], float t[3])
{
    float H[9];
    #pragma unroll
    for (int r = 0; r < 3; r++)
        #pragma unroll
        for (int c = 0; c < 3; c++)
            H[r*3+c] = P[r*3+c] - n*c1[r]*c2[c];

    // S = H^T H, V = I
    float S[3][3], V[3][3];
    #pragma unroll
    for (int r = 0; r < 3; r++)
        #pragma unroll
        for (int c = 0; c < 3; c++) {
            S[r][c] = H[0+r]*H[0+c] + H[3+r]*H[3+c] + H[6+r]*H[6+c];
            V[r][c] = (r == c) ? 1.f : 0.f;
        }
    float fro2 = 0.f;
    #pragma unroll
    for (int q = 0; q < 9; q++) fro2 += S[q/3][q%3]*S[q/3][q%3];
    const float tol = fro2 * 1e-12f;

    for (int sweep = 0; sweep < 10; sweep++) {
        float off = S[0][1]*S[0][1] + S[0][2]*S[0][2] + S[1][2]*S[1][2];
        if (off <= tol) break;
        #pragma unroll
        for (int pair = 0; pair < 3; pair++) {
            const int p = (pair == 2) ? 1 : 0;
            const int q = (pair == 0) ? 1 : 2;
            float apq = S[p][q];
            if (fabsf(apq) < 1e-30f) continue;
            float theta = (S[q][q] - S[p][p]) / (2.f*apq);
            float tj = ((theta >= 0.f) ? 1.f : -1.f) /
                       (fabsf(theta) + sqrtf(1.f + theta*theta));
            float cj = rsqrtf(1.f + tj*tj);
            float sj = tj*cj;
            #pragma unroll
            for (int k = 0; k < 3; k++) {
                float skp = S[k][p], skq = S[k][q];
                S[k][p] = cj*skp - sj*skq;
                S[k][q] = sj*skp + cj*skq;
            }
            #pragma unroll
            for (int k = 0; k < 3; k++) {
                float spk = S[p][k], sqk = S[q][k];
                S[p][k] = cj*spk - sj*sqk;
                S[q][k] = sj*spk + cj*sqk;
            }
            #pragma unroll
            for (int k = 0; k < 3; k++) {
                float vkp = V[k][p], vkq = V[k][q];
                V[k][p] = cj*vkp - sj*vkq;
                V[k][q] = sj*vkp + cj*vkq;
            }
        }
    }

    // sort eigenpairs descending
    float lam[3] = { S[0][0], S[1][1], S[2][2] };
    int ord[3] = {0,1,2};
    #pragma unroll
    for (int a = 0; a < 2; a++)
        #pragma unroll
        for (int b2_ = a+1; b2_ < 3; b2_++)
            if (lam[ord[b2_]] > lam[ord[a]]) { int tmp = ord[a]; ord[a] = ord[b2_]; ord[b2_] = tmp; }
    float Vs[3][3];
    #pragma unroll
    for (int c = 0; c < 3; c++)
        #pragma unroll
        for (int r = 0; r < 3; r++) Vs[r][c] = V[r][ord[c]];

    // U columns: u_i = H v_i / |H v_i|
    float U[3][3];
    #pragma unroll
    for (int c = 0; c < 3; c++) {
        float u0 = H[0]*Vs[0][c] + H[1]*Vs[1][c] + H[2]*Vs[2][c];
        float u1 = H[3]*Vs[0][c] + H[4]*Vs[1][c] + H[5]*Vs[2][c];
        float u2 = H[6]*Vs[0][c] + H[7]*Vs[1][c] + H[8]*Vs[2][c];
        float n2 = u0*u0 + u1*u1 + u2*u2;
        if (n2 > 1e-30f) {
            float inv = rsqrtf(n2);
            u0 *= inv; u1 *= inv; u2 *= inv;
        } else if (c == 2) {   // rank-deficient fallback: u2 = u0 x u1
            u0 = U[1][0]*U[2][1] - U[2][0]*U[1][1];
            u1 = U[2][0]*U[0][1] - U[0][0]*U[2][1];
            u2 = U[0][0]*U[1][1] - U[1][0]*U[0][1];
        }
        U[0][c] = u0; U[1][c] = u1; U[2][c] = u2;
    }
    float detV = Vs[0][0]*(Vs[1][1]*Vs[2][2]-Vs[1][2]*Vs[2][1])
               - Vs[0][1]*(Vs[1][0]*Vs[2][2]-Vs[1][2]*Vs[2][0])
               + Vs[0][2]*(Vs[1][0]*Vs[2][1]-Vs[1][1]*Vs[2][0]);
    float detU = U[0][0]*(U[1][1]*U[2][2]-U[1][2]*U[2][1])
               - U[0][1]*(U[1][0]*U[2][2]-U[1][2]*U[2][0])
               + U[0][2]*(U[1][0]*U[2][1]-U[1][1]*U[2][0]);
    float d = (detV*detU < 0.f) ? -1.f : 1.f;

    #pragma unroll
    for (int r = 0; r < 3; r++)
        #pragma unroll
        for (int c = 0; c < 3; c++)
            R[r*3+c] = Vs[r][0]*U[c][0] + Vs[r][1]*U[c][1] + d*Vs[r][2]*U[c][2];
    #pragma unroll
    for (int r = 0; r < 3; r++)
        t[r] = c2[r] - (R[r*3+0]*c1[0] + R[r*3+1]*c1[1] + R[r*3+2]*c1[2]);
}

// Shared reduction of 15 per-thread accumulators; returns them in sm15 (tid 0)
__device__ __forceinline__ void reduce15(float a[15], float sm15[15],
                                         float wsum[16][15], int tid)
{
    const int lane = tid & 31, wid = tid >> 5;
    #pragma unroll
    for (int q = 0; q < 15; q++)
        #pragma unroll
        for (int off = 16; off; off >>= 1)
            a[q] += __shfl_down_sync(0xffffffffu, a[q], off);
    if (lane == 0)
        #pragma unroll
        for (int q = 0; q < 15; q++) wsum[wid][q] = a[q];
    __syncthreads();
    if (wid == 0) {
        #pragma unroll
        for (int q = 0; q < 15; q++) a[q] = (lane < 16) ? wsum[lane][q] : 0.f;
        #pragma unroll
        for (int q = 0; q < 15; q++)
            #pragma unroll
            for (int off = 8; off; off >>= 1)
                a[q] += __shfl_down_sync(0xffffffffu, a[q], off);
        if (lane == 0)
            #pragma unroll
            for (int q = 0; q < 15; q++) sm15[q] = a[q];
    }
}

// ---------------------------------------------------------------------------
// K2: fused argmin-combine + gather + single-pass covariance + float Kabsch.
// Also resets g_best for the next iteration. grid=1, block=TPB2. Writes g_RT.
// ---------------------------------------------------------------------------
__global__ void __launch_bounds__(TPB2) k_solve(const float* __restrict__ src,
                                                const float* __restrict__ p2)
{
    __shared__ float wsum[16][15];
    __shared__ float sm15[15];
    const int tid = threadIdx.x;

    float a[15];
    #pragma unroll
    for (int q = 0; q < 15; q++) a[q] = 0.f;

    #pragma unroll
    for (int k = 0; k < NPTS/TPB2; k++) {
        int i = k*TPB2 + tid;
        unsigned long long key = g_best[i];
        g_best[i] = ~0ULL;               // reset for next iteration (own addr only)
        int idx = (int)(unsigned)(key & 0xFFFFFFFFu);
        float dx = p2[idx*3+0], dy = p2[idx*3+1], dz = p2[idx*3+2];
        float sx = src[i*3+0],  sy = src[i*3+1],  sz = src[i*3+2];
        a[0] += sx; a[1] += sy; a[2] += sz;
        a[3] += dx; a[4] += dy; a[5] += dz;
        a[6]  += sx*dx; a[7]  += sx*dy; a[8]  += sx*dz;
        a[9]  += sy*dx; a[10] += sy*dy; a[11] += sy*dz;
        a[12] += sz*dx; a[13] += sz*dy; a[14] += sz*dz;
    }
    reduce15(a, sm15, wsum, tid);
    if (tid == 0) {
        const float invN = 1.0f/NPTS;
        float c1[3] = { sm15[0]*invN, sm15[1]*invN, sm15[2]*invN };
        float c2[3] = { sm15[3]*invN, sm15[4]*invN, sm15[5]*invN };
        float R[9], t[3];
        kabsch3(&sm15[6], (float)NPTS, c1, c2, R, t);
        #pragma unroll
        for (int q = 0; q < 9; q++) g_RT[q] = R[q];
        g_RT[9] = t[0]; g_RT[10] = t[1]; g_RT[11] = t[2];
    }
}

// ---------------------------------------------------------------------------
// K3: final solve — Kabsch(p1 -> R*cur + t) with the last R,t applied on the
// fly (materializing pc_STEPS implicitly). Writes the [3,4] output.
// ---------------------------------------------------------------------------
__global__ void __launch_bounds__(TPB2) k_solve_final(const float* __restrict__ p1,
                                                      const float* __restrict__ cur,
                                                      float* __restrict__ out)
{
    __shared__ float wsum[16][15];
    __shared__ float sm15[15];
    const int tid = threadIdx.x;

    float r0=g_RT[0], r1=g_RT[1], r2=g_RT[2];
    float r3=g_RT[3], r4=g_RT[4], r5=g_RT[5];
    float r6=g_RT[6], r7=g_RT[7], r8=g_RT[8];
    float tx=g_RT[9], ty=g_RT[10], tz=g_RT[11];

    float a[15];
    #pragma unroll
    for (int q = 0; q < 15; q++) a[q] = 0.f;

    #pragma unroll
    for (int k = 0; k < NPTS/TPB2; k++) {
        int i = k*TPB2 + tid;
        float cx = cur[i*3+0], cy = cur[i*3+1], cz = cur[i*3+2];
        float dx = fmaf(r0,cx, fmaf(r1,cy, fmaf(r2,cz, tx)));
        float dy = fmaf(r3,cx, fmaf(r4,cy, fmaf(r5,cz, ty)));
        float dz = fmaf(r6,cx, fmaf(r7,cy, fmaf(r8,cz, tz)));
        float sx = p1[i*3+0], sy = p1[i*3+1], sz = p1[i*3+2];
        a[0] += sx; a[1] += sy; a[2] += sz;
        a[3] += dx; a[4] += dy; a[5] += dz;
        a[6]  += sx*dx; a[7]  += sx*dy; a[8]  += sx*dz;
        a[9]  += sy*dx; a[10] += sy*dy; a[11] += sy*dz;
        a[12] += sz*dx; a[13] += sz*dy; a[14] += sz*dz;
    }
    reduce15(a, sm15, wsum, tid);
    if (tid == 0) {
        const float invN = 1.0f/NPTS;
        float c1[3] = { sm15[0]*invN, sm15[1]*invN, sm15[2]*invN };
        float c2[3] = { sm15[3]*invN, sm15[4]*invN, sm15[5]*invN };
        float R[9], t[3];
        kabsch3(&sm15[6], (float)NPTS, c1, c2, R, t);
        #pragma unroll
        for (int r = 0; r < 3; r++) {
            out[r*4+0] = R[r*3+0];
            out[r*4+1] = R[r*3+1];
            out[r*4+2] = R[r*3+2];
            out[r*4+3] = t[r];
        }
    }
}

extern "C" void kernel_launch(void* const* d_in, const int* in_sizes, int n_in,
                              void* d_out, int out_size)
{
    const float* p1 = (const float*)d_in[0];
    const float* p2 = (const float*)d_in[1];
    float* out = (float*)d_out;

    float *A, *B;
    unsigned long long* BEST;
    cudaGetSymbolAddress((void**)&A, g_pcA);
    cudaGetSymbolAddress((void**)&B, g_pcB);
    cudaGetSymbolAddress((void**)&BEST, g_best);

    cudaMemcpyAsync(A, p1, NPTS*3*sizeof(float), cudaMemcpyDeviceToDevice, 0);
    cudaMemsetAsync(BEST, 0xFF, NPTS*sizeof(unsigned long long), 0);

    const dim3 nng(IBLK, JCH);

    // iteration 0: pc_0 already in A, no transform to apply
    k_nn<<<nng, TPB>>>(A, B, p2, 0);
    k_solve<<<1, TPB2>>>(A, p2);

    float* cur = A;  // holds pc_k at start of iteration k
    for (int k = 1; k < STEPS; k++) {
        float* inb  = cur;
        float* outb = (cur == A) ? B : A;
        k_nn<<<nng, TPB>>>(inb, outb, p2, 1);   // applies R_{k-1},t_{k-1}; jb==0 materializes pc_k
        k_solve<<<1, TPB2>>>(outb, p2);
        cur = outb;
    }

    // final: Kabsch(p1 -> R_9*pc_9 + t_9) writes the [3,4] output
    k_solve_final<<<1, TPB2>>>(p1, cur, out);
}

// round 3
// speedup vs baseline: 10.0270x; 1.1192x over previous
#include <cuda_runtime.h>

#define NPTS  4096
#define NCTA  128
#define TPB   256
#define IPC   32          // i-points per CTA
#define STEPS 10

// shared memory layout (bytes)
#define SM_SJ    0                       // float4[4096]  = 65536
#define SM_KEY   (NPTS*16)               // u64[32][32]   = 8192
#define SM_MYPC  (SM_KEY + 32*32*8)      // float[96]
#define SM_MYP1  (SM_MYPC + 96*4)        // float[96]
#define SM_SRT   (SM_MYP1 + 96*4)        // float[12] (+pad)
#define SM_SRED  (SM_SRT + 16*4)         // float[4][15]
#define SM_TOTAL (SM_SRED + 4*15*4 + 64)

// global scratch (no allocations allowed)
__device__ float g_part[NCTA][16];
__device__ float g_RT[12];
__device__ int   g_sync[64];   // [0..STEPS] arrival counters, [48] release flag

__device__ __forceinline__ unsigned int fkey(float f) {
    unsigned int u = __float_as_uint(f);
    return (u & 0x80000000u) ? ~u : (u | 0x80000000u);
}

// ---------------------------------------------------------------------------
// Float Kabsch from raw product sums P[r*3+c]=sum s_r d_c; H = P - n c1 c2^T.
// ---------------------------------------------------------------------------
__device__ void kabsch3(const float* __restrict__ P, float n,
                        const float c1[3], const float c2[3],
                        float R[9], float t[3])
{
    float H[9];
    #pragma unroll
    for (int r = 0; r < 3; r++)
        #pragma unroll
        for (int c = 0; c < 3; c++)
            H[r*3+c] = P[r*3+c] - n*c1[r]*c2[c];

    float S[3][3], V[3][3];
    #pragma unroll
    for (int r = 0; r < 3; r++)
        #pragma unroll
        for (int c = 0; c < 3; c++) {
            S[r][c] = H[0+r]*H[0+c] + H[3+r]*H[3+c] + H[6+r]*H[6+c];
            V[r][c] = (r == c) ? 1.f : 0.f;
        }
    float fro2 = 0.f;
    #pragma unroll
    for (int q = 0; q < 9; q++) fro2 += S[q/3][q%3]*S[q/3][q%3];
    const float tol = fro2 * 1e-12f;

    for (int sweep = 0; sweep < 10; sweep++) {
        float off = S[0][1]*S[0][1] + S[0][2]*S[0][2] + S[1][2]*S[1][2];
        if (off <= tol) break;
        #pragma unroll
        for (int pair = 0; pair < 3; pair++) {
            const int p = (pair == 2) ? 1 : 0;
            const int q = (pair == 0) ? 1 : 2;
            float apq = S[p][q];
            if (fabsf(apq) < 1e-30f) continue;
            float theta = (S[q][q] - S[p][p]) / (2.f*apq);
            float tj = ((theta >= 0.f) ? 1.f : -1.f) /
                       (fabsf(theta) + sqrtf(1.f + theta*theta));
            float cj = rsqrtf(1.f + tj*tj);
            float sj = tj*cj;
            #pragma unroll
            for (int k = 0; k < 3; k++) {
                float skp = S[k][p], skq = S[k][q];
                S[k][p] = cj*skp - sj*skq;
                S[k][q] = sj*skp + cj*skq;
            }
            #pragma unroll
            for (int k = 0; k < 3; k++) {
                float spk = S[p][k], sqk = S[q][k];
                S[p][k] = cj*spk - sj*sqk;
                S[q][k] = sj*spk + cj*sqk;
            }
            #pragma unroll
            for (int k = 0; k < 3; k++) {
                float vkp = V[k][p], vkq = V[k][q];
                V[k][p] = cj*vkp - sj*vkq;
                V[k][q] = sj*vkp + cj*vkq;
            }
        }
    }

    float lam[3] = { S[0][0], S[1][1], S[2][2] };
    int ord[3] = {0,1,2};
    #pragma unroll
    for (int a = 0; a < 2; a++)
        #pragma unroll
        for (int b = a+1; b < 3; b++)
            if (lam[ord[b]] > lam[ord[a]]) { int tmp = ord[a]; ord[a] = ord[b]; ord[b] = tmp; }
    float Vs[3][3];
    #pragma unroll
    for (int c = 0; c < 3; c++)
        #pragma unroll
        for (int r = 0; r < 3; r++) Vs[r][c] = V[r][ord[c]];

    float U[3][3];
    #pragma unroll
    for (int c = 0; c < 3; c++) {
        float u0 = H[0]*Vs[0][c] + H[1]*Vs[1][c] + H[2]*Vs[2][c];
        float u1 = H[3]*Vs[0][c] + H[4]*Vs[1][c] + H[5]*Vs[2][c];
        float u2 = H[6]*Vs[0][c] + H[7]*Vs[1][c] + H[8]*Vs[2][c];
        float n2 = u0*u0 + u1*u1 + u2*u2;
        if (n2 > 1e-30f) {
            float inv = rsqrtf(n2);
            u0 *= inv; u1 *= inv; u2 *= inv;
        } else if (c == 2) {
            u0 = U[1][0]*U[2][1] - U[2][0]*U[1][1];
            u1 = U[2][0]*U[0][1] - U[0][0]*U[2][1];
            u2 = U[0][0]*U[1][1] - U[1][0]*U[0][1];
        }
        U[0][c] = u0; U[1][c] = u1; U[2][c] = u2;
    }
    float detV = Vs[0][0]*(Vs[1][1]*Vs[2][2]-Vs[1][2]*Vs[2][1])
               - Vs[0][1]*(Vs[1][0]*Vs[2][2]-Vs[1][2]*Vs[2][0])
               + Vs[0][2]*(Vs[1][0]*Vs[2][1]-Vs[1][1]*Vs[2][0]);
    float detU = U[0][0]*(U[1][1]*U[2][2]-U[1][2]*U[2][1])
               - U[0][1]*(U[1][0]*U[2][2]-U[1][2]*U[2][0])
               + U[0][2]*(U[1][0]*U[2][1]-U[1][1]*U[2][0]);
    float d = (detV*detU < 0.f) ? -1.f : 1.f;

    #pragma unroll
    for (int r = 0; r < 3; r++)
        #pragma unroll
        for (int c = 0; c < 3; c++)
            R[r*3+c] = Vs[r][0]*U[c][0] + Vs[r][1]*U[c][1] + d*Vs[r][2]*U[c][2];
    #pragma unroll
    for (int r = 0; r < 3; r++)
        t[r] = c2[r] - (R[r*3+0]*c1[0] + R[r*3+1]*c1[1] + R[r*3+2]*c1[2]);
}

// warp-reduce 15 accumulators (full warp, fixed order -> deterministic)
__device__ __forceinline__ void wred15(float a[15]) {
    #pragma unroll
    for (int q = 0; q < 15; q++)
        #pragma unroll
        for (int off = 16; off; off >>= 1)
            a[q] += __shfl_down_sync(0xffffffffu, a[q], off);
}

// ---------------------------------------------------------------------------
// Persistent kernel: all STEPS iterations + final Kabsch. grid=NCTA, block=TPB.
// ---------------------------------------------------------------------------
__global__ void __launch_bounds__(TPB, 1)
icp_all(const float* __restrict__ p1, const float* __restrict__ p2,
        float* __restrict__ out)
{
    extern __shared__ unsigned char smem[];
    float4*             sj   = (float4*)(smem + SM_SJ);
    unsigned long long* key  = (unsigned long long*)(smem + SM_KEY);
    float*              mypc = (float*)(smem + SM_MYPC);
    float*              myp1 = (float*)(smem + SM_MYP1);
    float*              srt  = (float*)(smem + SM_SRT);
    float*              sred = (float*)(smem + SM_SRED);

    const int cta = blockIdx.x;
    const int tid = threadIdx.x;

    // load p2 (+ precomputed 0.5|q|^2) into shared; reused all iterations
    for (int j = tid; j < NPTS; j += TPB) {
        float qx = p2[j*3+0], qy = p2[j*3+1], qz = p2[j*3+2];
        sj[j] = make_float4(qx, qy, qz, 0.5f*fmaf(qx,qx,fmaf(qy,qy,qz*qz)));
    }
    if (tid < IPC) {
        int i = cta*IPC + tid;
        float x = p1[i*3+0], y = p1[i*3+1], z = p1[i*3+2];
        myp1[tid*3+0] = x; myp1[tid*3+1] = y; myp1[tid*3+2] = z;
        mypc[tid*3+0] = x; mypc[tid*3+1] = y; mypc[tid*3+2] = z;
    }
    __syncthreads();

    const int iblk  = tid & 7;        // 8 i-blocks of 4 points
    const int slice = tid >> 3;       // 32 j-slices of 128
    const int ib4   = iblk*4;

    for (int k = 0; k <= STEPS; k++) {
        // apply R_{k-1}, t_{k-1}: pc_k = R pc_{k-1} + t
        if (k > 0 && tid < IPC) {
            float x = mypc[tid*3+0], y = mypc[tid*3+1], z = mypc[tid*3+2];
            float nx = fmaf(srt[0],x, fmaf(srt[1],y, fmaf(srt[2],z, srt[9])));
            float ny = fmaf(srt[3],x, fmaf(srt[4],y, fmaf(srt[5],z, srt[10])));
            float nz = fmaf(srt[6],x, fmaf(srt[7],y, fmaf(srt[8],z, srt[11])));
            mypc[tid*3+0] = nx; mypc[tid*3+1] = ny; mypc[tid*3+2] = nz;
        }
        __syncthreads();

        if (k < STEPS) {
            // --- NN: 4 i-points x 128 j per thread, score = |q|^2/2 - p.q ---
            float x0=mypc[(ib4+0)*3+0], y0=mypc[(ib4+0)*3+1], z0=mypc[(ib4+0)*3+2];
            float x1=mypc[(ib4+1)*3+0], y1=mypc[(ib4+1)*3+1], z1=mypc[(ib4+1)*3+2];
            float x2=mypc[(ib4+2)*3+0], y2=mypc[(ib4+2)*3+1], z2=mypc[(ib4+2)*3+2];
            float x3=mypc[(ib4+3)*3+0], y3=mypc[(ib4+3)*3+1], z3=mypc[(ib4+3)*3+2];

            float b0=3.4028235e38f, b1=b0, b2=b0, b3=b0;
            int   j0=0, j1=0, j2=0, j3=0;
            const int jbeg = slice*128;
            #pragma unroll 8
            for (int jj = jbeg; jj < jbeg + 128; jj++) {
                float4 q = sj[jj];
                float s0 = fmaf(-x0,q.x, fmaf(-y0,q.y, fmaf(-z0,q.z, q.w)));
                float s1 = fmaf(-x1,q.x, fmaf(-y1,q.y, fmaf(-z1,q.z, q.w)));
                float s2 = fmaf(-x2,q.x, fmaf(-y2,q.y, fmaf(-z2,q.z, q.w)));
                float s3 = fmaf(-x3,q.x, fmaf(-y3,q.y, fmaf(-z3,q.z, q.w)));
                if (s0 < b0) { b0 = s0; j0 = jj; }   // strict <: first index on ties
                if (s1 < b1) { b1 = s1; j1 = jj; }
                if (s2 < b2) { b2 = s2; j2 = jj; }
                if (s3 < b3) { b3 = s3; j3 = jj; }
            }
            key[slice*32 + ib4+0] = ((unsigned long long)fkey(b0) << 32) | (unsigned)j0;
            key[slice*32 + ib4+1] = ((unsigned long long)fkey(b1) << 32) | (unsigned)j1;
            key[slice*32 + ib4+2] = ((unsigned long long)fkey(b2) << 32) | (unsigned)j2;
            key[slice*32 + ib4+3] = ((unsigned long long)fkey(b3) << 32) | (unsigned)j3;
            __syncthreads();
        }

        // --- per-CTA covariance partials (warp 0) ---
        if (tid < 32) {
            float sx, sy, sz, dx, dy, dz;
            if (k < STEPS) {
                unsigned long long best = key[tid];
                #pragma unroll 8
                for (int s2 = 1; s2 < 32; s2++) {
                    unsigned long long v = key[s2*32 + tid];
                    if (v < best) best = v;   // (score, j) lexicographic: first-index ties
                }
                const int idx = (int)(unsigned)(best & 0xFFFFFFFFu);
                float4 q = sj[idx];
                dx = q.x; dy = q.y; dz = q.z;
                sx = mypc[tid*3+0]; sy = mypc[tid*3+1]; sz = mypc[tid*3+2];
            } else {
                sx = myp1[tid*3+0]; sy = myp1[tid*3+1]; sz = myp1[tid*3+2];
                dx = mypc[tid*3+0]; dy = mypc[tid*3+1]; dz = mypc[tid*3+2];
            }
            float a[15];
            a[0]=sx; a[1]=sy; a[2]=sz; a[3]=dx; a[4]=dy; a[5]=dz;
            a[6]=sx*dx; a[7]=sx*dy; a[8]=sx*dz;
            a[9]=sy*dx; a[10]=sy*dy; a[11]=sy*dz;
            a[12]=sz*dx; a[13]=sz*dy; a[14]=sz*dz;
            wred15(a);
            if (tid == 0) {
                volatile float* gp = g_part[cta];
                #pragma unroll
                for (int q = 0; q < 15; q++) gp[q] = a[q];
                __threadfence();
                atomicAdd(&g_sync[k], 1);
            }
        }

        // --- CTA0: global reduce + Kabsch + publish ---
        if (cta == 0) {
            if (tid == 0) {
                while (((volatile int*)g_sync)[k] < NCTA) __nanosleep(32);
            }
            __syncthreads();
            __threadfence();
            float a[15];
            if (tid < NCTA) {
                volatile float* gp = g_part[tid];
                #pragma unroll
                for (int q = 0; q < 15; q++) a[q] = gp[q];
            } else {
                #pragma unroll
                for (int q = 0; q < 15; q++) a[q] = 0.f;
            }
            wred15(a);
            if ((tid & 31) == 0 && tid < NCTA) {
                #pragma unroll
                for (int q = 0; q < 15; q++) sred[(tid>>5)*15 + q] = a[q];
            }
            __syncthreads();
            if (tid == 0) {
                float s15[15];
                #pragma unroll
                for (int q = 0; q < 15; q++)
                    s15[q] = sred[q] + sred[15+q] + sred[30+q] + sred[45+q];
                const float invN = 1.0f/NPTS;
                float c1[3] = { s15[0]*invN, s15[1]*invN, s15[2]*invN };
                float c2[3] = { s15[3]*invN, s15[4]*invN, s15[5]*invN };
                float R[9], t[3];
                kabsch3(&s15[6], (float)NPTS, c1, c2, R, t);
                if (k < STEPS) {
                    volatile float* grt = g_RT;
                    #pragma unroll
                    for (int q = 0; q < 9; q++) grt[q] = R[q];
                    grt[9]=t[0]; grt[10]=t[1]; grt[11]=t[2];
                    __threadfence();
                    ((volatile int*)g_sync)[48] = k + 1;   // release
                } else {
                    #pragma unroll
                    for (int r = 0; r < 3; r++) {
                        out[r*4+0]=R[r*3+0]; out[r*4+1]=R[r*3+1];
                        out[r*4+2]=R[r*3+2]; out[r*4+3]=t[r];
                    }
                }
            }
        }

        // --- all CTAs pick up the published R,t ---
        if (k < STEPS) {
            if (tid == 0) {
                while (((volatile int*)g_sync)[48] < k + 1) __nanosleep(32);
            }
            __syncthreads();
            __threadfence();
            if (tid < 12) srt[tid] = ((volatile float*)g_RT)[tid];
            __syncthreads();
        }
    }
}

extern "C" void kernel_launch(void* const* d_in, const int* in_sizes, int n_in,
                              void* d_out, int out_size)
{
    const float* p1 = (const float*)d_in[0];
    const float* p2 = (const float*)d_in[1];
    float* out = (float*)d_out;

    int* SYNC;
    cudaGetSymbolAddress((void**)&SYNC, g_sync);
    cudaMemsetAsync(SYNC, 0, 64*sizeof(int), 0);

    static int attr_set = 0;
    if (!attr_set) {
        cudaFuncSetAttribute(icp_all, cudaFuncAttributeMaxDynamicSharedMemorySize,
                             SM_TOTAL);
        attr_set = 1;
    }
    icp_all<<<NCTA, TPB, SM_TOTAL>>>(p1, p2, out);
}